// round 16
// baseline (speedup 1.0000x reference)
#include <cuda_runtime.h>
#include <cuda_fp16.h>
#include <cstdint>

#define NN 10000
#define NE 40000
#define NG 64
#define H  64
#define QC 4160    // 65 rows x 64 cols: 64 theta rows + 1 b2 row
#define NTB 33     // n-blocks of 128 (4224 padded)

typedef unsigned long long ull;

// ---------------- scratch ----------------
__device__ float  g_h0[NN*H];
__device__ float  g_h1[NN*H];
__device__ __half g_Qh[(size_t)NN*QC];    // fp16 Q (~83MB)
__device__ float  g_agg[NN*H];
__device__ float  g_Bfrag[NTB*4096];      // per n-block: 16KB of fp16 B fragments
__device__ float  g_invdeg[NN];
__device__ float  g_hg[NG*H];
__device__ float  g_gcnt[NG];
__device__ int    g_cnt[NN];
__device__ int    g_cstart[NN+1];
__device__ int    g_ideg[NN];
__device__ int    g_perm[NE];
__device__ int    g_dsts[NE];
__device__ float  g_eas[NE*16];

__device__ __forceinline__ float siluf(float x){
    return x * (1.0f/(1.0f+__expf(-x)));
}
__device__ __forceinline__ uint32_t s2u(const void* p){
    return (uint32_t)__cvta_generic_to_shared(p);
}
__device__ __forceinline__ uint32_t f2hh(float a, float b){
    __half2 h = __floats2half2_rn(a, b);
    return *(uint32_t*)&h;
}

// ---------------- node-side [*,64]@[64,64] with fused epilogue ----------------
__global__ void k_nodemm(const float* __restrict__ A, float* __restrict__ out,
                         const float* __restrict__ W, const float* __restrict__ b,
                         int mode){
    __shared__ float Ws[H*H];
    __shared__ float As[64][H+1];
    int t = threadIdx.x;
    int base = blockIdx.x*64;
    for(int i=t;i<H*H;i+=256) Ws[i]=W[i];
    for(int i=t;i<64*H;i+=256){
        int r=i>>6, c=i&63; int v=base+r;
        As[r][c] = (v<NN) ? A[v*H+c] : 0.f;
    }
    __syncthreads();
    int vl=t>>2, ob=(t&3)*16;
    int v=base+vl;
    if(v>=NN) return;
    float acc[16];
    #pragma unroll
    for(int q=0;q<16;q++) acc[q]=b[ob+q];
    #pragma unroll 8
    for(int i=0;i<H;i++){
        float hv=As[vl][i];
        #pragma unroll
        for(int q=0;q<16;q++) acc[q] += hv*Ws[i*H+ob+q];
    }
    if(mode==0){
        #pragma unroll
        for(int q=0;q<16;q++) out[v*H+ob+q]=acc[q];
    } else {
        float inv = g_invdeg[v];
        #pragma unroll
        for(int q=0;q<16;q++){
            float val = g_agg[v*H+ob+q]*inv + acc[q];
            out[v*H+ob+q] = siluf(val);
        }
    }
}

// ---------------- build fp16 B fragments for qgemm ----------------
__global__ void k_transp(const float* __restrict__ w2, const float* __restrict__ b2){
    int idx = blockIdx.x*256 + threadIdx.x;
    if(idx >= NTB*4*16*32) return;
    int lane = idx & 31;
    int nt   = (idx>>5) & 15;
    int kt   = (idx>>9) & 3;
    int tile = idx >> 11;
    int n  = tile*128 + nt*8 + (lane>>2);
    int kb = kt*16 + (lane&3)*2;
    float v[4];
    #pragma unroll
    for(int q=0;q<4;q++){
        int k = kb + (q&1) + ((q>>1)<<3);
        float val = 0.f;
        if(n < 4096)      val = w2[(n>>6)*4096 + k*64 + (n&63)];
        else if(n < QC)   val = b2[k*64 + (n-4096)];
        v[q] = val;
    }
    uint2 hv = make_uint2(f2hh(v[0],v[1]), f2hh(v[2],v[3]));
    uint2* bp = (uint2*)g_Bfrag;
    bp[(size_t)tile*2048 + (size_t)((kt*16+nt)*32 + lane)] = hv;
}

// ---------------- histograms ----------------
__global__ void k_hist(const int* __restrict__ ei){
    int e = blockIdx.x*256 + threadIdx.x;
    if(e < NE){
        atomicAdd(&g_cnt[ei[e]], 1);
        atomicAdd(&g_ideg[ei[NE+e]], 1);
    }
}

// ---------------- Q = h @ W2ext via mma.sync fp16, fp16 output ----------------
__global__ void __launch_bounds__(256,2) k_qgemm(const float* __restrict__ hin){
    extern __shared__ char sm[];
    uint32_t sbase = s2u(sm);
    int t = threadIdx.x;
    int lane = t & 31;
    int w = t >> 5;
    int bn = blockIdx.x;
    int bm = blockIdx.y*128;

    {
        const float4* bsrc = (const float4*)(g_Bfrag + (size_t)bn*4096);
        float4* bdst = (float4*)(sm + 16384);
        for(int i=t;i<1024;i+=256) bdst[i] = bsrc[i];
    }
    {
        int mt = w;
        int m0 = bm + mt*16 + (lane>>2);
        int m1 = m0 + 8;
        int c2 = (lane&3)*2;
        const float* h0p = hin + (size_t)m0*H;
        const float* h1p = hin + (size_t)m1*H;
        bool val0 = (m0 < NN), val1 = (m1 < NN);
        #pragma unroll
        for(int kt=0; kt<4; kt++){
            int kb = kt*16 + c2;
            float2 f00 = val0 ? *(const float2*)(h0p + kb)     : make_float2(0.f,0.f);
            float2 f01 = val0 ? *(const float2*)(h0p + kb + 8) : make_float2(0.f,0.f);
            float2 f10 = val1 ? *(const float2*)(h1p + kb)     : make_float2(0.f,0.f);
            float2 f11 = val1 ? *(const float2*)(h1p + kb + 8) : make_float2(0.f,0.f);
            uint4 v;
            v.x = f2hh(f00.x, f00.y);
            v.y = f2hh(f10.x, f10.y);
            v.z = f2hh(f01.x, f01.y);
            v.w = f2hh(f11.x, f11.y);
            *(uint4*)(sm + ((kt*8 + mt)*32 + lane)*16) = v;
        }
    }
    __syncthreads();

    int warpM = w>>2;
    int warpN = w&3;
    float d[16][4];
    #pragma unroll
    for(int i=0;i<16;i++)
        #pragma unroll
        for(int j=0;j<4;j++) d[i][j]=0.f;

    #pragma unroll
    for(int kt=0; kt<4; kt++){
        uint32_t a[4][4], b[4][2];
        #pragma unroll
        for(int i=0;i<4;i++){
            uint32_t addr = sbase + (uint32_t)(((kt*8 + warpM*4 + i)*32 + lane)*16);
            asm volatile("ld.shared.v4.b32 {%0,%1,%2,%3}, [%4];"
                : "=r"(a[i][0]),"=r"(a[i][1]),"=r"(a[i][2]),"=r"(a[i][3]) : "r"(addr));
        }
        #pragma unroll
        for(int j=0;j<4;j++){
            uint32_t addr = sbase + 16384u + (uint32_t)(((kt*16 + warpN*4 + j)*32 + lane)*8);
            asm volatile("ld.shared.v2.b32 {%0,%1}, [%2];"
                : "=r"(b[j][0]),"=r"(b[j][1]) : "r"(addr));
        }
        #pragma unroll
        for(int i=0;i<4;i++)
            #pragma unroll
            for(int j=0;j<4;j++){
                asm volatile(
                  "mma.sync.aligned.m16n8k16.row.col.f32.f16.f16.f32 "
                  "{%0,%1,%2,%3}, {%4,%5,%6,%7}, {%8,%9}, {%0,%1,%2,%3};"
                  : "+f"(d[i*4+j][0]),"+f"(d[i*4+j][1]),"+f"(d[i*4+j][2]),"+f"(d[i*4+j][3])
                  : "r"(a[i][0]),"r"(a[i][1]),"r"(a[i][2]),"r"(a[i][3]),
                    "r"(b[j][0]),"r"(b[j][1]));
            }
    }

    #pragma unroll
    for(int i=0;i<4;i++){
        int row0 = bm + warpM*64 + i*16 + (lane>>2);
        #pragma unroll
        for(int j=0;j<4;j++){
            int col = bn*128 + warpN*32 + j*8 + (lane&3)*2;
            if(col < QC){
                if(row0 < NN)
                    *(__half2*)(g_Qh + (size_t)row0*QC + col) = __floats2half2_rn(d[i*4+j][0], d[i*4+j][1]);
                if(row0+8 < NN)
                    *(__half2*)(g_Qh + (size_t)(row0+8)*QC + col) = __floats2half2_rn(d[i*4+j][2], d[i*4+j][3]);
            }
        }
    }
}

// ---------------- scan (+ fused invdeg, keeps cstart) ----------------
__global__ void k_scan(){
    __shared__ int sp[1024];
    int t = threadIdx.x;
    const int CH = 10;
    int base = t*CH;
    int loc[CH];
    int sum = 0;
    #pragma unroll
    for(int i=0;i<CH;i++){
        int idx = base+i;
        int v = (idx < NN) ? g_cnt[idx] : 0;
        loc[i] = sum; sum += v;
    }
    sp[t] = sum;
    __syncthreads();
    for(int d=1; d<1024; d<<=1){
        int v = (t >= d) ? sp[t-d] : 0;
        __syncthreads();
        sp[t] += v;
        __syncthreads();
    }
    int off = (t > 0) ? sp[t-1] : 0;
    #pragma unroll
    for(int i=0;i<CH;i++){
        int idx = base+i;
        if(idx < NN){
            int st = off + loc[i];
            g_cnt[idx] = st;
            g_cstart[idx] = st;
            int d = g_ideg[idx];
            g_invdeg[idx] = (d > 0) ? 1.0f/(float)d : 0.0f;
        }
    }
    if(t == 0) g_cstart[NN] = NE;
}

__global__ void k_scatter(const int* __restrict__ ei){
    int e = blockIdx.x*256 + threadIdx.x;
    if(e < NE){
        int s = ei[e];
        int pos = atomicAdd(&g_cnt[s], 1);
        g_dsts[pos] = ei[NE+e];
        g_perm[pos] = e;
    }
}

__global__ void k_gatherEA(const float* __restrict__ ea){
    int idx = blockIdx.x*256 + threadIdx.x;
    if(idx < NE*16){
        g_eas[idx] = ea[g_perm[idx>>4]*16 + (idx&15)];
    }
}

// ---------------- per-src-node message via mma: warp = one src node ----------------
// smem: W1s(4096) b1s(256) then per-warp { Qs[65][72] halves (9360B), SFs[16][64] halves (2048B) }
#define MSG_WARPBYTES (9360 + 2048)
#define MSG_SMEM (4352 + 8*MSG_WARPBYTES)
__global__ void __launch_bounds__(256) k_msg(const float* __restrict__ w1, const float* __restrict__ b1){
    extern __shared__ char sm[];
    float* W1s = (float*)sm;                 // [16][64]
    float* b1s = (float*)(sm + 4096);        // [64]
    int t = threadIdx.x;
    int lane = t & 31;
    int w = t >> 5;
    for(int i=t;i<16*64;i+=256) W1s[i]=w1[i];
    if(t<64) b1s[t]=b1[t];
    __syncthreads();

    int v = blockIdx.x*8 + w;
    if(v >= NN) return;
    int es = g_cstart[v];
    int dv = g_cstart[v+1] - es;
    if(dv == 0) return;

    char* wb = sm + 4352 + w*MSG_WARPBYTES;
    __half* Qs  = (__half*)wb;               // 65 rows, stride 72 halves (144B)
    __half* SFs = (__half*)(wb + 9360);      // 16 rows, stride 64 halves
    uint32_t qsu  = s2u(Qs);

    // stage Q row-block [65][64] -> padded [65][72]
    {
        const __half* src = g_Qh + (size_t)v*QC;
        for(int i=lane; i<520; i+=32){
            int row = i>>3, c8 = i&7;
            *(uint4*)(Qs + row*72 + c8*8) = *(const uint4*)(src + row*64 + c8*8);
        }
    }
    __syncwarp();

    int m  = lane>>2;
    int c2 = (lane&3)*2;

    for(int base=0; base<dv; base+=16){
        int nb = dv - base; if(nb > 16) nb = 16;
        __syncwarp();
        // sfeat rows 0..nb-1 cooperatively (f32 compute, fp16 store)
        for(int idx=lane; idx<nb*64; idx+=32){
            int r = idx>>6, j = idx&63;
            const float* ea = g_eas + (size_t)(es+base+r)*16;
            float4 e0 = *(const float4*)(ea);
            float4 e1 = *(const float4*)(ea+4);
            float4 e2 = *(const float4*)(ea+8);
            float4 e3 = *(const float4*)(ea+12);
            float s = b1s[j];
            s += e0.x*W1s[ 0*64+j] + e0.y*W1s[ 1*64+j] + e0.z*W1s[ 2*64+j] + e0.w*W1s[ 3*64+j];
            s += e1.x*W1s[ 4*64+j] + e1.y*W1s[ 5*64+j] + e1.z*W1s[ 6*64+j] + e1.w*W1s[ 7*64+j];
            s += e2.x*W1s[ 8*64+j] + e2.y*W1s[ 9*64+j] + e2.z*W1s[10*64+j] + e2.w*W1s[11*64+j];
            s += e3.x*W1s[12*64+j] + e3.y*W1s[13*64+j] + e3.z*W1s[14*64+j] + e3.w*W1s[15*64+j];
            SFs[r*64+j] = __float2half_rn(siluf(s));
        }
        // zero rows nb..15
        for(int r=nb; r<16; r++) ((uint32_t*)SFs)[r*32 + lane] = 0u;
        __syncwarp();

        // A fragments: direct LDS.32 (sf row-major pairs)
        uint32_t a[4][4];
        #pragma unroll
        for(int kt=0; kt<4; kt++){
            a[kt][0] = *(uint32_t*)(SFs +  m   *64 + kt*16 + c2);
            a[kt][1] = *(uint32_t*)(SFs + (m+8)*64 + kt*16 + c2);
            a[kt][2] = *(uint32_t*)(SFs +  m   *64 + kt*16 + c2 + 8);
            a[kt][3] = *(uint32_t*)(SFs + (m+8)*64 + kt*16 + c2 + 8);
        }

        float d[8][4];
        #pragma unroll
        for(int i=0;i<8;i++){ d[i][0]=0.f; d[i][1]=0.f; d[i][2]=0.f; d[i][3]=0.f; }

        int tl = lane>>3, trow = lane&7;
        #pragma unroll
        for(int ntp=0; ntp<4; ntp++){
            #pragma unroll
            for(int kt=0; kt<4; kt++){
                int k0 = kt*16 + ((tl&1)<<3);
                int n0 = ntp*16 + ((tl>>1)<<3);
                uint32_t addr = qsu + (uint32_t)(((k0+trow)*72 + n0)*2);
                uint32_t b0,b1r,b2r,b3r;
                asm volatile("ldmatrix.sync.aligned.m8n8.x4.trans.shared.b16 {%0,%1,%2,%3}, [%4];"
                    : "=r"(b0),"=r"(b1r),"=r"(b2r),"=r"(b3r) : "r"(addr));
                asm volatile(
                  "mma.sync.aligned.m16n8k16.row.col.f32.f16.f16.f32 "
                  "{%0,%1,%2,%3}, {%4,%5,%6,%7}, {%8,%9}, {%0,%1,%2,%3};"
                  : "+f"(d[ntp*2][0]),"+f"(d[ntp*2][1]),"+f"(d[ntp*2][2]),"+f"(d[ntp*2][3])
                  : "r"(a[kt][0]),"r"(a[kt][1]),"r"(a[kt][2]),"r"(a[kt][3]),
                    "r"(b0),"r"(b1r));
                asm volatile(
                  "mma.sync.aligned.m16n8k16.row.col.f32.f16.f16.f32 "
                  "{%0,%1,%2,%3}, {%4,%5,%6,%7}, {%8,%9}, {%0,%1,%2,%3};"
                  : "+f"(d[ntp*2+1][0]),"+f"(d[ntp*2+1][1]),"+f"(d[ntp*2+1][2]),"+f"(d[ntp*2+1][3])
                  : "r"(a[kt][0]),"r"(a[kt][1]),"r"(a[kt][2]),"r"(a[kt][3]),
                    "r"(b2r),"r"(b3r));
            }
        }

        // epilogue: rows m, m+8 within this 16-row batch
        int r0 = m;
        bool act0 = (base + r0    ) < dv;
        bool act1 = (base + r0 + 8) < dv;
        int dst0 = act0 ? g_dsts[es + base + r0    ] : 0;
        int dst1 = act1 ? g_dsts[es + base + r0 + 8] : 0;
        #pragma unroll
        for(int nt=0; nt<8; nt++){
            int c0 = nt*8 + c2;
            float2 qb2 = __half22float2(*(__half2*)(Qs + 64*72 + c0));
            if(act0){
                atomicAdd(g_agg + dst0*64 + c0,     d[nt][0] + qb2.x);
                atomicAdd(g_agg + dst0*64 + c0 + 1, d[nt][1] + qb2.y);
            }
            if(act1){
                atomicAdd(g_agg + dst1*64 + c0,     d[nt][2] + qb2.x);
                atomicAdd(g_agg + dst1*64 + c0 + 1, d[nt][3] + qb2.y);
            }
        }
    }
}

// ---------------- global mean pool ----------------
__global__ void k_pool(const int* __restrict__ batch, const float* __restrict__ hfin){
    int idx = blockIdx.x*256 + threadIdx.x;
    if(idx < NN*H){
        int v = idx>>6, o = idx&63;
        int g = batch[v];
        atomicAdd(&g_hg[g*H + o], hfin[idx]);
        if(o == 0) atomicAdd(&g_gcnt[g], 1.0f);
    }
}

// ---------------- head MLP ----------------
__global__ void k_head(const float* __restrict__ w1, const float* __restrict__ b1,
                       const float* __restrict__ w2, const float* __restrict__ b2,
                       float* __restrict__ out){
    __shared__ float W1s[64*64];
    __shared__ float hgn[64*64];
    __shared__ float t1[64*64];
    int t = threadIdx.x;
    for(int i=t;i<4096;i+=256) W1s[i]=w1[i];
    for(int i=t;i<4096;i+=256){
        int g = i>>6;
        float c = g_gcnt[g];
        hgn[i] = g_hg[i] / fmaxf(c, 1.0f);
    }
    __syncthreads();
    int g = t>>2, ob = (t&3)*16;
    float acc[16];
    #pragma unroll
    for(int q=0;q<16;q++) acc[q]=b1[ob+q];
    for(int i=0;i<64;i++){
        float hv = hgn[g*64+i];
        #pragma unroll
        for(int q=0;q<16;q++) acc[q] += hv*W1s[i*64+ob+q];
    }
    #pragma unroll
    for(int q=0;q<16;q++) t1[g*64+ob+q] = siluf(acc[q]);
    __syncthreads();
    if(t < 64){
        float s = b2[0];
        for(int o=0;o<64;o++) s += t1[t*64+o]*w2[o];
        out[t] = s;
    }
}

// ---------------- launch ----------------
extern "C" void kernel_launch(void* const* d_in, const int* in_sizes, int n_in,
                              void* d_out, int out_size){
    const float* x         = (const float*)d_in[0];
    const float* edge_attr = (const float*)d_in[1];
    const int*   edge_index= (const int*)  d_in[2];
    const int*   batch     = (const int*)  d_in[3];
    const float* proj_w    = (const float*)d_in[4];
    const float* proj_b    = (const float*)d_in[5];
    const float* edge_w1   = (const float*)d_in[6];
    const float* edge_b1   = (const float*)d_in[7];
    const float* edge_w2   = (const float*)d_in[8];
    const float* edge_b2   = (const float*)d_in[9];
    const float* root_w    = (const float*)d_in[10];
    const float* conv_b    = (const float*)d_in[11];
    const float* head_w1   = (const float*)d_in[12];
    const float* head_b1   = (const float*)d_in[13];
    const float* head_w2   = (const float*)d_in[14];
    const float* head_b2   = (const float*)d_in[15];
    float* out = (float*)d_out;

    void *p_agg, *p_hg, *p_gcnt, *p_h0, *p_h1, *p_cnt, *p_ideg;
    cudaGetSymbolAddress(&p_agg,  g_agg);
    cudaGetSymbolAddress(&p_hg,   g_hg);
    cudaGetSymbolAddress(&p_gcnt, g_gcnt);
    cudaGetSymbolAddress(&p_h0,   g_h0);
    cudaGetSymbolAddress(&p_h1,   g_h1);
    cudaGetSymbolAddress(&p_cnt,  g_cnt);
    cudaGetSymbolAddress(&p_ideg, g_ideg);
    float* h0 = (float*)p_h0;
    float* h1 = (float*)p_h1;

    const int QSMEM = 32*1024;
    cudaFuncSetAttribute(k_qgemm, cudaFuncAttributeMaxDynamicSharedMemorySize, QSMEM);
    cudaFuncSetAttribute(k_msg,   cudaFuncAttributeMaxDynamicSharedMemorySize, MSG_SMEM);

    cudaMemsetAsync(p_cnt,  0, NN*sizeof(int));
    cudaMemsetAsync(p_ideg, 0, NN*sizeof(int));
    cudaMemsetAsync(p_hg,   0, NG*H*sizeof(float));
    cudaMemsetAsync(p_gcnt, 0, NG*sizeof(float));

    float* cur = h0;
    float* nxt = h1;

    // launch order: profiler's fixed 4th-kernel capture lands on k_qgemm
    k_nodemm<<<(NN+63)/64, 256>>>(x, cur, proj_w, proj_b, 0);                     // 1
    k_transp<<<(NTB*4*16*32+255)/256, 256>>>(edge_w2, edge_b2);                   // 2
    k_hist<<<(NE+255)/256, 256>>>(edge_index);                                    // 3
    k_qgemm<<<dim3(NTB, (NN+127)/128), 256, QSMEM>>>(cur);                        // 4 (profiled)
    k_scan<<<1, 1024>>>();                                                        // 5
    k_scatter<<<(NE+255)/256, 256>>>(edge_index);                                 // 6
    k_gatherEA<<<(NE*16+255)/256, 256>>>(edge_attr);                              // 7

    for(int l=0;l<3;l++){
        if(l > 0){
            k_transp<<<(NTB*4*16*32+255)/256, 256>>>(edge_w2 + (size_t)l*64*4096, edge_b2 + (size_t)l*4096);
            k_qgemm<<<dim3(NTB, (NN+127)/128), 256, QSMEM>>>(cur);
        }
        cudaMemsetAsync(p_agg, 0, (size_t)NN*H*sizeof(float));
        k_msg<<<(NN+7)/8, 256, MSG_SMEM>>>(edge_w1 + (size_t)l*16*64, edge_b1 + (size_t)l*64);
        k_nodemm<<<(NN+63)/64, 256>>>(cur, nxt, root_w + (size_t)l*64*64, conv_b + (size_t)l*64, 1);
        float* tmp = cur; cur = nxt; nxt = tmp;
    }

    k_pool<<<(NN*H+255)/256, 256>>>(batch, cur);
    k_head<<<1, 256>>>(head_w1, head_b1, head_w2, head_b2, out);
}

// round 17
// speedup vs baseline: 1.2177x; 1.2177x over previous
#include <cuda_runtime.h>
#include <cuda_fp16.h>
#include <cstdint>

#define NN 10000
#define NE 40000
#define NG 64
#define H  64
#define QC 4160    // 64*64 theta cols + 64 b2 cols
#define NTB 33     // n-blocks of 128 (4224 padded)

typedef unsigned long long ull;

// ---------------- scratch ----------------
__device__ float  g_h0[NN*H];
__device__ float  g_h1[NN*H];
__device__ __half g_Qh[(size_t)NN*QC];    // fp16 Q (~83MB)
__device__ float  g_agg[NN*H];
__device__ float  g_Bfrag[NTB*4096];      // per n-block: 16KB of fp16 B fragments
__device__ float  g_invdeg[NN];
__device__ float  g_hg[NG*H];
__device__ float  g_gcnt[NG];
__device__ int    g_cnt[NN];
__device__ int    g_ideg[NN];
__device__ int    g_perm[NE];
__device__ int    g_srcs[NE];
__device__ int    g_dsts[NE];
__device__ float  g_eas[NE*16];

__device__ __forceinline__ float siluf(float x){
    return x * (1.0f/(1.0f+__expf(-x)));
}
__device__ __forceinline__ uint32_t s2u(const void* p){
    return (uint32_t)__cvta_generic_to_shared(p);
}
__device__ __forceinline__ uint32_t f2hh(float a, float b){
    __half2 h = __floats2half2_rn(a, b);
    return *(uint32_t*)&h;
}

// ---------------- node-side [*,64]@[64,64] with fused epilogue ----------------
__global__ void k_nodemm(const float* __restrict__ A, float* __restrict__ out,
                         const float* __restrict__ W, const float* __restrict__ b,
                         int mode){
    __shared__ float Ws[H*H];
    __shared__ float As[64][H+1];
    int t = threadIdx.x;
    int base = blockIdx.x*64;
    for(int i=t;i<H*H;i+=256) Ws[i]=W[i];
    for(int i=t;i<64*H;i+=256){
        int r=i>>6, c=i&63; int v=base+r;
        As[r][c] = (v<NN) ? A[v*H+c] : 0.f;
    }
    __syncthreads();
    int vl=t>>2, ob=(t&3)*16;
    int v=base+vl;
    if(v>=NN) return;
    float acc[16];
    #pragma unroll
    for(int q=0;q<16;q++) acc[q]=b[ob+q];
    #pragma unroll 8
    for(int i=0;i<H;i++){
        float hv=As[vl][i];
        #pragma unroll
        for(int q=0;q<16;q++) acc[q] += hv*Ws[i*H+ob+q];
    }
    if(mode==0){
        #pragma unroll
        for(int q=0;q<16;q++) out[v*H+ob+q]=acc[q];
    } else {
        float inv = g_invdeg[v];
        #pragma unroll
        for(int q=0;q<16;q++){
            float val = g_agg[v*H+ob+q]*inv + acc[q];
            out[v*H+ob+q] = siluf(val);
        }
    }
}

// ---------------- build fp16 B fragments: one thread = one 8B fragment slot ----------------
__global__ void k_transp(const float* __restrict__ w2, const float* __restrict__ b2){
    int idx = blockIdx.x*256 + threadIdx.x;
    if(idx >= NTB*4*16*32) return;
    int lane = idx & 31;
    int nt   = (idx>>5) & 15;
    int kt   = (idx>>9) & 3;
    int tile = idx >> 11;
    int n  = tile*128 + nt*8 + (lane>>2);
    int kb = kt*16 + (lane&3)*2;
    float v[4];
    #pragma unroll
    for(int q=0;q<4;q++){
        int k = kb + (q&1) + ((q>>1)<<3);   // kb, kb+1, kb+8, kb+9
        float val = 0.f;
        if(n < 4096)      val = w2[(n>>6)*4096 + k*64 + (n&63)];
        else if(n < QC)   val = b2[k*64 + (n-4096)];
        v[q] = val;
    }
    uint2 hv = make_uint2(f2hh(v[0],v[1]), f2hh(v[2],v[3]));
    uint2* bp = (uint2*)g_Bfrag;
    bp[(size_t)tile*2048 + (size_t)((kt*16+nt)*32 + lane)] = hv;
}

// ---------------- histograms ----------------
__global__ void k_hist(const int* __restrict__ ei){
    int e = blockIdx.x*256 + threadIdx.x;
    if(e < NE){
        atomicAdd(&g_cnt[ei[e]], 1);
        atomicAdd(&g_ideg[ei[NE+e]], 1);
    }
}

// ---------------- Q = h @ W2ext via mma.sync fp16; smem-staged coalesced epilogue ----------------
// smem: phase1 = A frags 16KB + B frags 16KB; phase2 (reuse) = D tile 128 x 136 halves (34816B)
#define QSMEM 34816
__global__ void __launch_bounds__(256,2) k_qgemm(const float* __restrict__ hin){
    extern __shared__ char sm[];
    uint32_t sbase = s2u(sm);
    int t = threadIdx.x;
    int lane = t & 31;
    int w = t >> 5;
    int bn = blockIdx.x;
    int bm = blockIdx.y*128;

    // B fragments: straight 16KB copy
    {
        const float4* bsrc = (const float4*)(g_Bfrag + (size_t)bn*4096);
        float4* bdst = (float4*)(sm + 16384);
        for(int i=t;i<1024;i+=256) bdst[i] = bsrc[i];
    }
    // A fragments: warp w = m-tile w; lane = fragment lane. Conflict-free STS.128.
    {
        int mt = w;
        int m0 = bm + mt*16 + (lane>>2);
        int m1 = m0 + 8;
        int c2 = (lane&3)*2;
        const float* h0p = hin + (size_t)m0*H;
        const float* h1p = hin + (size_t)m1*H;
        bool val0 = (m0 < NN), val1 = (m1 < NN);
        #pragma unroll
        for(int kt=0; kt<4; kt++){
            int kb = kt*16 + c2;
            float2 f00 = val0 ? *(const float2*)(h0p + kb)     : make_float2(0.f,0.f);
            float2 f01 = val0 ? *(const float2*)(h0p + kb + 8) : make_float2(0.f,0.f);
            float2 f10 = val1 ? *(const float2*)(h1p + kb)     : make_float2(0.f,0.f);
            float2 f11 = val1 ? *(const float2*)(h1p + kb + 8) : make_float2(0.f,0.f);
            uint4 v;
            v.x = f2hh(f00.x, f00.y);
            v.y = f2hh(f10.x, f10.y);
            v.z = f2hh(f01.x, f01.y);
            v.w = f2hh(f11.x, f11.y);
            *(uint4*)(sm + ((kt*8 + mt)*32 + lane)*16) = v;
        }
    }
    __syncthreads();

    int warpM = w>>2;
    int warpN = w&3;
    float d[16][4];
    #pragma unroll
    for(int i=0;i<16;i++)
        #pragma unroll
        for(int j=0;j<4;j++) d[i][j]=0.f;

    #pragma unroll
    for(int kt=0; kt<4; kt++){
        uint32_t a[4][4], b[4][2];
        #pragma unroll
        for(int i=0;i<4;i++){
            uint32_t addr = sbase + (uint32_t)(((kt*8 + warpM*4 + i)*32 + lane)*16);
            asm volatile("ld.shared.v4.b32 {%0,%1,%2,%3}, [%4];"
                : "=r"(a[i][0]),"=r"(a[i][1]),"=r"(a[i][2]),"=r"(a[i][3]) : "r"(addr));
        }
        #pragma unroll
        for(int j=0;j<4;j++){
            uint32_t addr = sbase + 16384u + (uint32_t)(((kt*16 + warpN*4 + j)*32 + lane)*8);
            asm volatile("ld.shared.v2.b32 {%0,%1}, [%2];"
                : "=r"(b[j][0]),"=r"(b[j][1]) : "r"(addr));
        }
        #pragma unroll
        for(int i=0;i<4;i++)
            #pragma unroll
            for(int j=0;j<4;j++){
                asm volatile(
                  "mma.sync.aligned.m16n8k16.row.col.f32.f16.f16.f32 "
                  "{%0,%1,%2,%3}, {%4,%5,%6,%7}, {%8,%9}, {%0,%1,%2,%3};"
                  : "+f"(d[i*4+j][0]),"+f"(d[i*4+j][1]),"+f"(d[i*4+j][2]),"+f"(d[i*4+j][3])
                  : "r"(a[i][0]),"r"(a[i][1]),"r"(a[i][2]),"r"(a[i][3]),
                    "r"(b[j][0]),"r"(b[j][1]));
            }
    }

    // epilogue phase 1: D -> padded smem tile (conflict-free STS.32)
    __syncthreads();
    __half* Eh = (__half*)sm;          // [128][136]
    #pragma unroll
    for(int i=0;i<4;i++){
        int r0 = warpM*64 + i*16 + (lane>>2);
        #pragma unroll
        for(int j=0;j<4;j++){
            int c = warpN*32 + j*8 + (lane&3)*2;
            *(__half2*)(Eh + (size_t)r0*136 + c)     = __floats2half2_rn(d[i*4+j][0], d[i*4+j][1]);
            *(__half2*)(Eh + (size_t)(r0+8)*136 + c) = __floats2half2_rn(d[i*4+j][2], d[i*4+j][3]);
        }
    }
    __syncthreads();

    // epilogue phase 2: coalesced copy-out (uint4 = 8 halves)
    for(int i=t; i<2048; i+=256){
        int r  = i>>4;
        int c8 = i&15;
        int gr = bm + r;
        int gc = bn*128 + c8*8;
        if(gr < NN && gc < QC){
            *(uint4*)(g_Qh + (size_t)gr*QC + gc) = *(uint4*)(Eh + (size_t)r*136 + c8*8);
        }
    }
}

// ---------------- scan (+ fused invdeg) ----------------
__global__ void k_scan(){
    __shared__ int sp[1024];
    int t = threadIdx.x;
    const int CH = 10;
    int base = t*CH;
    int loc[CH];
    int sum = 0;
    #pragma unroll
    for(int i=0;i<CH;i++){
        int idx = base+i;
        int v = (idx < NN) ? g_cnt[idx] : 0;
        loc[i] = sum; sum += v;
    }
    sp[t] = sum;
    __syncthreads();
    for(int d=1; d<1024; d<<=1){
        int v = (t >= d) ? sp[t-d] : 0;
        __syncthreads();
        sp[t] += v;
        __syncthreads();
    }
    int off = (t > 0) ? sp[t-1] : 0;
    #pragma unroll
    for(int i=0;i<CH;i++){
        int idx = base+i;
        if(idx < NN){
            g_cnt[idx] = off + loc[i];
            int d = g_ideg[idx];
            g_invdeg[idx] = (d > 0) ? 1.0f/(float)d : 0.0f;
        }
    }
}

__global__ void k_scatter(const int* __restrict__ ei){
    int e = blockIdx.x*256 + threadIdx.x;
    if(e < NE){
        int s = ei[e];
        int pos = atomicAdd(&g_cnt[s], 1);
        g_srcs[pos] = s;
        g_dsts[pos] = ei[NE+e];
        g_perm[pos] = e;
    }
}

__global__ void k_gatherEA(const float* __restrict__ ea){
    int idx = blockIdx.x*256 + threadIdx.x;
    if(idx < NE*16){
        g_eas[idx] = ea[g_perm[idx>>4]*16 + (idx&15)];
    }
}

// ---------------- per-edge message: 32 edges/block, 8 lanes/edge, LDG.128 ----------------
__global__ void k_msg(const float* __restrict__ w1, const float* __restrict__ b1){
    __shared__ float W1s[16*64];
    __shared__ float b1s[64];
    __shared__ float eas[32][17];
    __shared__ float sf[32][65];
    __shared__ int   ss[32], ds[32];
    int t = threadIdx.x;
    int e0 = blockIdx.x*32;

    for(int i=t;i<16*64;i+=256) W1s[i]=w1[i];
    if(t<64) b1s[t]=b1[t];
    #pragma unroll
    for(int i=t;i<512;i+=256){
        int sl = i>>4, c = i&15;
        int e = e0 + sl;
        eas[sl][c] = (e<NE) ? g_eas[e*16 + c] : 0.f;
    }
    if(t<32){
        int e = e0 + t;
        ss[t] = (e<NE) ? g_srcs[e] : 0;
        ds[t] = (e<NE) ? g_dsts[e] : 0;
    }
    __syncthreads();

    int s = t>>3, l = t&7, o0 = l*8;
    {
        float v[8];
        #pragma unroll
        for(int q=0;q<8;q++) v[q]=b1s[o0+q];
        #pragma unroll
        for(int j=0;j<16;j++){
            float ej = eas[s][j];
            #pragma unroll
            for(int q=0;q<8;q++) v[q] += ej*W1s[j*64+o0+q];
        }
        #pragma unroll
        for(int q=0;q<8;q++) sf[s][o0+q] = siluf(v[q]);
    }
    __syncthreads();

    int e = e0 + s;
    if(e < NE){
        const __half* q = g_Qh + (size_t)ss[s]*QC;
        float a[8];
        {
            uint4 raw = *(const uint4*)(q + 4096 + o0);
            float2 f0 = __half22float2(*(const __half2*)&raw.x);
            float2 f1 = __half22float2(*(const __half2*)&raw.y);
            float2 f2 = __half22float2(*(const __half2*)&raw.z);
            float2 f3 = __half22float2(*(const __half2*)&raw.w);
            a[0]=f0.x; a[1]=f0.y; a[2]=f1.x; a[3]=f1.y;
            a[4]=f2.x; a[5]=f2.y; a[6]=f3.x; a[7]=f3.y;
        }
        #pragma unroll 8
        for(int j=0;j<64;j++){
            uint4 raw = *(const uint4*)(q + j*64 + o0);
            float sj = sf[s][j];
            float2 f0 = __half22float2(*(const __half2*)&raw.x);
            float2 f1 = __half22float2(*(const __half2*)&raw.y);
            float2 f2 = __half22float2(*(const __half2*)&raw.z);
            float2 f3 = __half22float2(*(const __half2*)&raw.w);
            a[0] += sj*f0.x; a[1] += sj*f0.y;
            a[2] += sj*f1.x; a[3] += sj*f1.y;
            a[4] += sj*f2.x; a[5] += sj*f2.y;
            a[6] += sj*f3.x; a[7] += sj*f3.y;
        }
        float* ap = g_agg + ds[s]*H + o0;
        #pragma unroll
        for(int q=0;q<8;q++) atomicAdd(ap+q, a[q]);
    }
}

// ---------------- global mean pool ----------------
__global__ void k_pool(const int* __restrict__ batch, const float* __restrict__ hfin){
    int idx = blockIdx.x*256 + threadIdx.x;
    if(idx < NN*H){
        int v = idx>>6, o = idx&63;
        int g = batch[v];
        atomicAdd(&g_hg[g*H + o], hfin[idx]);
        if(o == 0) atomicAdd(&g_gcnt[g], 1.0f);
    }
}

// ---------------- head MLP ----------------
__global__ void k_head(const float* __restrict__ w1, const float* __restrict__ b1,
                       const float* __restrict__ w2, const float* __restrict__ b2,
                       float* __restrict__ out){
    __shared__ float W1s[64*64];
    __shared__ float hgn[64*64];
    __shared__ float t1[64*64];
    int t = threadIdx.x;
    for(int i=t;i<4096;i+=256) W1s[i]=w1[i];
    for(int i=t;i<4096;i+=256){
        int g = i>>6;
        float c = g_gcnt[g];
        hgn[i] = g_hg[i] / fmaxf(c, 1.0f);
    }
    __syncthreads();
    int g = t>>2, ob = (t&3)*16;
    float acc[16];
    #pragma unroll
    for(int q=0;q<16;q++) acc[q]=b1[ob+q];
    for(int i=0;i<64;i++){
        float hv = hgn[g*64+i];
        #pragma unroll
        for(int q=0;q<16;q++) acc[q] += hv*W1s[i*64+ob+q];
    }
    #pragma unroll
    for(int q=0;q<16;q++) t1[g*64+ob+q] = siluf(acc[q]);
    __syncthreads();
    if(t < 64){
        float s = b2[0];
        for(int o=0;o<64;o++) s += t1[t*64+o]*w2[o];
        out[t] = s;
    }
}

// ---------------- launch ----------------
extern "C" void kernel_launch(void* const* d_in, const int* in_sizes, int n_in,
                              void* d_out, int out_size){
    const float* x         = (const float*)d_in[0];
    const float* edge_attr = (const float*)d_in[1];
    const int*   edge_index= (const int*)  d_in[2];
    const int*   batch     = (const int*)  d_in[3];
    const float* proj_w    = (const float*)d_in[4];
    const float* proj_b    = (const float*)d_in[5];
    const float* edge_w1   = (const float*)d_in[6];
    const float* edge_b1   = (const float*)d_in[7];
    const float* edge_w2   = (const float*)d_in[8];
    const float* edge_b2   = (const float*)d_in[9];
    const float* root_w    = (const float*)d_in[10];
    const float* conv_b    = (const float*)d_in[11];
    const float* head_w1   = (const float*)d_in[12];
    const float* head_b1   = (const float*)d_in[13];
    const float* head_w2   = (const float*)d_in[14];
    const float* head_b2   = (const float*)d_in[15];
    float* out = (float*)d_out;

    void *p_agg, *p_hg, *p_gcnt, *p_h0, *p_h1, *p_cnt, *p_ideg;
    cudaGetSymbolAddress(&p_agg,  g_agg);
    cudaGetSymbolAddress(&p_hg,   g_hg);
    cudaGetSymbolAddress(&p_gcnt, g_gcnt);
    cudaGetSymbolAddress(&p_h0,   g_h0);
    cudaGetSymbolAddress(&p_h1,   g_h1);
    cudaGetSymbolAddress(&p_cnt,  g_cnt);
    cudaGetSymbolAddress(&p_ideg, g_ideg);
    float* h0 = (float*)p_h0;
    float* h1 = (float*)p_h1;

    cudaFuncSetAttribute(k_qgemm, cudaFuncAttributeMaxDynamicSharedMemorySize, QSMEM);

    cudaMemsetAsync(p_cnt,  0, NN*sizeof(int));
    cudaMemsetAsync(p_ideg, 0, NN*sizeof(int));
    cudaMemsetAsync(p_hg,   0, NG*H*sizeof(float));
    cudaMemsetAsync(p_gcnt, 0, NG*sizeof(float));

    float* cur = h0;
    float* nxt = h1;

    // launch order: profiler's fixed capture slot lands on k_qgemm
    k_nodemm<<<(NN+63)/64, 256>>>(x, cur, proj_w, proj_b, 0);                     // 1
    k_transp<<<(NTB*4*16*32+255)/256, 256>>>(edge_w2, edge_b2);                   // 2
    k_hist<<<(NE+255)/256, 256>>>(edge_index);                                    // 3
    k_qgemm<<<dim3(NTB, (NN+127)/128), 256, QSMEM>>>(cur);                        // 4 (profiled)
    k_scan<<<1, 1024>>>();                                                        // 5
    k_scatter<<<(NE+255)/256, 256>>>(edge_index);                                 // 6
    k_gatherEA<<<(NE*16+255)/256, 256>>>(edge_attr);                              // 7

    for(int l=0;l<3;l++){
        if(l > 0){
            k_transp<<<(NTB*4*16*32+255)/256, 256>>>(edge_w2 + (size_t)l*64*4096, edge_b2 + (size_t)l*4096);
            k_qgemm<<<dim3(NTB, (NN+127)/128), 256, QSMEM>>>(cur);
        }
        cudaMemsetAsync(p_agg, 0, (size_t)NN*H*sizeof(float));
        k_msg<<<(NE+31)/32, 256>>>(edge_w1 + (size_t)l*16*64, edge_b1 + (size_t)l*64);
        k_nodemm<<<(NN+63)/64, 256>>>(cur, nxt, root_w + (size_t)l*64*64, conv_b + (size_t)l*64, 1);
        float* tmp = cur; cur = nxt; nxt = tmp;
    }

    k_pool<<<(NN*H+255)/256, 256>>>(batch, cur);
    k_head<<<1, 256>>>(head_w1, head_b1, head_w2, head_b2, out);
}